// round 14
// baseline (speedup 1.0000x reference)
#include <cuda_runtime.h>
#include <cstdint>
#include <math.h>

// Problem constants: B=1024, H=32, N=25, F=D=128
#define BH      32768
#define G       152                 // 1 block/SM x 152 SMs
#define THREADS 256
#define NGRP    3                   // mbar groups (4 slots each)
#define NSLOT   12
#define RS4     33                  // padded row stride in float4 (132 floats)
#define SLOT_F4 (26 * RS4)          // 858 float4 per slot (~13.7 KB)
#define ROW_BYTES 13312             // 26 x 512 staged bytes per row
#define MAXIT   27                  // ceil(216 rows per block / 8)

typedef unsigned long long ull;

// ---------------------------------------------------------------------------
__device__ __forceinline__ void tma_bulk_1d(unsigned dst, const void* src,
                                            unsigned bytes, unsigned mbar) {
    asm volatile(
        "cp.async.bulk.shared::cluster.global.mbarrier::complete_tx::bytes "
        "[%0], [%1], %2, [%3];\n"
        :: "r"(dst), "l"(src), "r"(bytes), "r"(mbar) : "memory");
}
__device__ __forceinline__ void mbar_init(unsigned mbar, unsigned cnt) {
    asm volatile("mbarrier.init.shared.b64 [%0], %1;\n" :: "r"(mbar), "r"(cnt) : "memory");
}
__device__ __forceinline__ void mbar_expect_tx(unsigned mbar, unsigned bytes) {
    asm volatile("mbarrier.arrive.expect_tx.shared.b64 _, [%0], %1;\n"
                 :: "r"(mbar), "r"(bytes) : "memory");
}
__device__ __forceinline__ void mbar_wait(unsigned mbar, unsigned parity) {
    asm volatile(
        "{\n\t"
        ".reg .pred P;\n\t"
        "WL_%=:\n\t"
        "mbarrier.try_wait.parity.acquire.cta.shared::cta.b64 P, [%0], %1, 0x989680;\n\t"
        "@P bra WD_%=;\n\t"
        "bra WL_%=;\n\t"
        "WD_%=:\n\t"
        "}"
        :: "r"(mbar), "r"(parity) : "memory");
}

__global__ void __launch_bounds__(THREADS, 1)
fused_gat_kernel(const float* __restrict__ x_self,
                 const float* __restrict__ x_neigh,
                 const float* __restrict__ W,
                 const float* __restrict__ a_s,
                 const float* __restrict__ a_n,
                 float* __restrict__ out) {
    // padded tile ring: slot = 26 rows x 132 floats (rows 0-24 = neigh, 25 = self)
    __shared__ __align__(16) float4 xs[NSLOT * SLOT_F4];        // ~165 KB
    __shared__ __align__(16) float4 wa4[2 * RS4];               // wa_n @0, wa_s @RS4
    __shared__ __align__(16) float  xagg_il[2][8][128];         // double-buffered
    __shared__ __align__(8)  ull    mbars[NGRP];

    const int t    = threadIdx.x;
    const int warp = t >> 5;
    const int lane = t & 31;
    const int b    = blockIdx.x;

    const unsigned xs_base   = (unsigned)__cvta_generic_to_shared(&xs[0]);
    const unsigned mbar_base = (unsigned)__cvta_generic_to_shared(&mbars[0]);
    float* wa_f = reinterpret_cast<float*>(wa4);

    if (t == 0) {
#pragma unroll
        for (int i = 0; i < NGRP; i++) mbar_init(mbar_base + 8 * i, 1);
        asm volatile("fence.proxy.async.shared::cta;\n" ::: "memory");
    }

    // ---------------- prologue: wa = W @ a  (2 threads per f) ----------------
    {
        const int f  = t >> 1, hf = t & 1;
        const float* wr = W + (size_t)f * 128 + hf * 64;
        const float* as = a_s + hf * 64;
        const float* an = a_n + hf * 64;
        float vs = 0.f, vn = 0.f;
#pragma unroll
        for (int j = 0; j < 64; j++) {
            float w = wr[j];
            vs = fmaf(w, as[j], vs);
            vn = fmaf(w, an[j], vn);
        }
        vs += __shfl_xor_sync(0xffffffffu, vs, 1);
        vn += __shfl_xor_sync(0xffffffffu, vn, 1);
        if (!hf) { wa_f[f] = vn; wa_f[4 * RS4 + f] = vs; }   // wa_n, wa_s (132-f apart)
    }

    // W register cache, packed f32x2 along f (GEMV): warp covers d = warp*16+(lane&15)
    const int h = lane >> 4;
    const int d = warp * 16 + (lane & 15);
    ull Wreg2[32];
#pragma unroll
    for (int i = 0; i < 32; i++) {
        int f = h * 64 + 2 * i;
        unsigned lo = __float_as_uint(W[(size_t)f * 128 + d]);
        unsigned hi = __float_as_uint(W[(size_t)(f + 1) * 128 + d]);
        Wreg2[i] = ((ull)hi << 32) | lo;
    }
    __syncthreads();    // mbars + wa visible

    // slot filler: 26 bulk copies (25 neigh rows + self) into padded layout
    auto fill_slot = [&](int slot, int row, unsigned mb) {
        unsigned dst = xs_base + (unsigned)slot * (SLOT_F4 * 16);
        const float* xn = x_neigh + (size_t)row * 3200;
#pragma unroll
        for (int rr = 0; rr < 25; rr++)
            tma_bulk_1d(dst + rr * (RS4 * 16), xn + rr * 128, 512, mb);
        tma_bulk_1d(dst + 25 * (RS4 * 16), x_self + (size_t)row * 128, 512, mb);
    };
    auto group_fill = [&](int c, int j) {   // consumption index c, slot-in-group j
        int grp = c % NGRP;
        int r0  = b + 4 * c * G;
        unsigned mb = mbar_base + 8 * grp;
        if (j == 0 && r0 < BH) {
            int nv = (BH - 1 - r0) / G + 1;
            nv = (nv > 4) ? 4 : nv;
            mbar_expect_tx(mb, (unsigned)(nv * ROW_BYTES));
        }
        int row = r0 + j * G;
        if (row < BH) fill_slot(grp * 4 + j, row, mb);
    };

    // initial fill: consumption groups 0,1,2
    if (t < 12) group_fill(t >> 2, t & 3);

    // ---------------- main loop: 8 rows per iteration, 1 row per warp ----------------
    for (int i = 0; i < MAXIT; i++) {
        const int myrow = b + (8 * i + warp) * G;
        if (myrow < BH) {
            const int c   = 2 * i + (warp >> 2);
            const int grp = c % NGRP;
            mbar_wait(mbar_base + 8 * grp, (unsigned)((c / NGRP) & 1));

            const float4* sp = &xs[(grp * 4 + (warp & 3)) * SLOT_F4];

            // ---- scores: lane k owns dot k (0-24 neigh, 25 self·wa_n, 26 self·wa_s)
            const int rowk = (lane < 25) ? lane : 25;
            const float4* xr = sp + rowk * RS4;
            const float4* wv = &wa4[(lane == 26) ? RS4 : 0];
            float a0 = 0.f, a1 = 0.f, a2 = 0.f, a3 = 0.f;
#pragma unroll
            for (int m = 0; m < 32; m += 4) {
                float4 x0 = xr[m],     w0 = wv[m];
                float4 x1 = xr[m + 1], w1 = wv[m + 1];
                float4 x2 = xr[m + 2], w2 = wv[m + 2];
                float4 x3 = xr[m + 3], w3 = wv[m + 3];
                a0 = fmaf(x0.x, w0.x, a0); a0 = fmaf(x0.y, w0.y, a0);
                a0 = fmaf(x0.z, w0.z, a0); a0 = fmaf(x0.w, w0.w, a0);
                a1 = fmaf(x1.x, w1.x, a1); a1 = fmaf(x1.y, w1.y, a1);
                a1 = fmaf(x1.z, w1.z, a1); a1 = fmaf(x1.w, w1.w, a1);
                a2 = fmaf(x2.x, w2.x, a2); a2 = fmaf(x2.y, w2.y, a2);
                a2 = fmaf(x2.z, w2.z, a2); a2 = fmaf(x2.w, w2.w, a2);
                a3 = fmaf(x3.x, w3.x, a3); a3 = fmaf(x3.y, w3.y, a3);
                a3 = fmaf(x3.z, w3.z, a3); a3 = fmaf(x3.w, w3.w, a3);
            }
            float v  = (a0 + a1) + (a2 + a3);
            float ss = __shfl_sync(0xffffffffu, v, 26);
            float u  = ss + v;
            u = (u > 0.f) ? u : 0.2f * u;                 // LeakyReLU(0.2)
            float e = (lane < 26) ? __expf(u) : 0.f;      // no-max softmax (validated)
            float z = e;
#pragma unroll
            for (int o = 16; o; o >>= 1) z += __shfl_xor_sync(0xffffffffu, z, o);
            const float rz = __fdividef(1.f, z);

            // ---- aggregation: lane covers f = 4*lane..4*lane+3, e via shfl.idx
            float c0 = 0.f, c1 = 0.f, c2 = 0.f, c3 = 0.f;
#pragma unroll
            for (int k2 = 0; k2 < 26; k2++) {
                float ek = __shfl_sync(0xffffffffu, e, k2);
                float4 xv = sp[k2 * RS4 + lane];          // coalesced, conflict-free
                c0 = fmaf(ek, xv.x, c0); c1 = fmaf(ek, xv.y, c1);
                c2 = fmaf(ek, xv.z, c2); c3 = fmaf(ek, xv.w, c3);
            }
            c0 *= rz; c1 *= rz; c2 *= rz; c3 *= rz;

            // interleaved store for the conflict-free GEMV read pattern
            float* xp = &xagg_il[i & 1][warp][0];
            const int Lb = (lane < 16) ? 8 * lane : 8 * (lane - 16) + 4;
            *reinterpret_cast<float2*>(&xp[Lb])     = make_float2(c0, c1);
            *reinterpret_cast<float2*>(&xp[Lb + 2]) = make_float2(c2, c3);
        }
        __syncthreads();    // xagg ready; tiles of groups (2i)%3,(2i+1)%3 dead

        // refill the two consumed groups for consumption indices 2i+3, 2i+4
        if (t < 8) group_fill(2 * i + 3 + (t >> 2), t & 3);

        // ---- GEMV: all warps, 8 rows, from packed register W ----
        const float* xbuf = &xagg_il[i & 1][0][0];
#pragma unroll
        for (int r = 0; r < 8; r++) {
            const int orow = b + (8 * i + r) * G;
            if (orow < BH) {
                ull A0 = 0, A1 = 0;
                const float* xg = xbuf + r * 128;
#pragma unroll
                for (int ii = 0; ii < 16; ii++) {
                    longlong2 q = *reinterpret_cast<const longlong2*>(&xg[8 * ii + 4 * h]);
                    asm volatile("fma.rn.f32x2 %0, %1, %2, %0;\n"
                                 : "+l"(A0) : "l"((ull)q.x), "l"(Wreg2[2 * ii]));
                    asm volatile("fma.rn.f32x2 %0, %1, %2, %0;\n"
                                 : "+l"(A1) : "l"((ull)q.y), "l"(Wreg2[2 * ii + 1]));
                }
                float o = __uint_as_float((unsigned)A0) +
                          __uint_as_float((unsigned)(A0 >> 32)) +
                          __uint_as_float((unsigned)A1) +
                          __uint_as_float((unsigned)(A1 >> 32));
                o += __shfl_xor_sync(0xffffffffu, o, 16);   // combine f-halves
                if (h == 0)
                    out[(size_t)orow * 128 + d] = (o > 0.f) ? o : 0.f;
            }
        }
        // no second barrier: next iteration writes xagg_il[(i+1)&1] (double buffer)
    }
}

// ---------------------------------------------------------------------------
extern "C" void kernel_launch(void* const* d_in, const int* in_sizes, int n_in,
                              void* d_out, int out_size) {
    const float* x_self  = (const float*)d_in[0];   // [1024,32,128]
    const float* x_neigh = (const float*)d_in[1];   // [1024,32,25,128]
    const float* w_feat  = (const float*)d_in[2];   // [128,128]
    const float* a_self  = (const float*)d_in[3];   // [128,1]
    const float* a_neigh = (const float*)d_in[4];   // [128,1]
    float*       out     = (float*)d_out;           // [1024,32,128]

    fused_gat_kernel<<<G, THREADS>>>(x_self, x_neigh, w_feat,
                                     a_self, a_neigh, out);
}

// round 15
// speedup vs baseline: 1.4787x; 1.4787x over previous
#include <cuda_runtime.h>
#include <cstdint>
#include <math.h>

// Problem constants: B=1024, H=32, N=25, F=D=128
#define BH      32768
#define G       152                 // 1 block/SM x 152 SMs
#define THREADS 256
#define NGRP    3                   // mbar groups (4 slots each)
#define NSLOT   12
#define RS4     33                  // padded row stride in float4 (132 floats)
#define SLOT_F4 (26 * RS4)          // 858 float4 per slot (~13.7 KB)
#define ROW_BYTES 13312             // 26 x 512 staged bytes per row
#define MAXIT   27                  // ceil(216 rows per block / 8)

typedef unsigned long long ull;

// ---------------------------------------------------------------------------
__device__ __forceinline__ void tma_bulk_1d(unsigned dst, const void* src,
                                            unsigned bytes, unsigned mbar) {
    asm volatile(
        "cp.async.bulk.shared::cluster.global.mbarrier::complete_tx::bytes "
        "[%0], [%1], %2, [%3];\n"
        :: "r"(dst), "l"(src), "r"(bytes), "r"(mbar) : "memory");
}
__device__ __forceinline__ void mbar_init(unsigned mbar, unsigned cnt) {
    asm volatile("mbarrier.init.shared.b64 [%0], %1;\n" :: "r"(mbar), "r"(cnt) : "memory");
}
__device__ __forceinline__ void mbar_expect_tx(unsigned mbar, unsigned bytes) {
    asm volatile("mbarrier.arrive.expect_tx.shared.b64 _, [%0], %1;\n"
                 :: "r"(mbar), "r"(bytes) : "memory");
}
__device__ __forceinline__ void mbar_wait(unsigned mbar, unsigned parity) {
    asm volatile(
        "{\n\t"
        ".reg .pred P;\n\t"
        "WL_%=:\n\t"
        "mbarrier.try_wait.parity.acquire.cta.shared::cta.b64 P, [%0], %1, 0x989680;\n\t"
        "@P bra WD_%=;\n\t"
        "bra WL_%=;\n\t"
        "WD_%=:\n\t"
        "}"
        :: "r"(mbar), "r"(parity) : "memory");
}

__global__ void __launch_bounds__(THREADS, 2)   // reg target 128 (smem limits to 1 block)
fused_gat_kernel(const float* __restrict__ x_self,
                 const float* __restrict__ x_neigh,
                 const float* __restrict__ W,
                 const float* __restrict__ a_s,
                 const float* __restrict__ a_n,
                 float* __restrict__ out) {
    // padded tile ring: slot = 26 rows x 132 floats (rows 0-24 = neigh, 25 = self)
    __shared__ __align__(16) float4 xs[NSLOT * SLOT_F4];        // ~165 KB
    __shared__ __align__(16) float4 wa4[2 * RS4];               // wa_n @0, wa_s @RS4
    __shared__ __align__(16) float  xagg_il[2][8][128];         // double-buffered
    __shared__ __align__(8)  ull    mbars[NGRP];

    const int t    = threadIdx.x;
    const int warp = t >> 5;
    const int lane = t & 31;
    const int b    = blockIdx.x;

    const unsigned xs_base   = (unsigned)__cvta_generic_to_shared(&xs[0]);
    const unsigned mbar_base = (unsigned)__cvta_generic_to_shared(&mbars[0]);
    float* wa_f = reinterpret_cast<float*>(wa4);

    if (t == 0) {
#pragma unroll
        for (int i = 0; i < NGRP; i++) mbar_init(mbar_base + 8 * i, 1);
        asm volatile("fence.proxy.async.shared::cta;\n" ::: "memory");
    }

    // ---------------- prologue: wa = W @ a  (2 threads per f) ----------------
    {
        const int f  = t >> 1, hf = t & 1;
        const float* wr = W + (size_t)f * 128 + hf * 64;
        const float* as = a_s + hf * 64;
        const float* an = a_n + hf * 64;
        float vs = 0.f, vn = 0.f;
#pragma unroll 16
        for (int j = 0; j < 64; j++) {
            float w = wr[j];
            vs = fmaf(w, as[j], vs);
            vn = fmaf(w, an[j], vn);
        }
        vs += __shfl_xor_sync(0xffffffffu, vs, 1);
        vn += __shfl_xor_sync(0xffffffffu, vn, 1);
        if (!hf) { wa_f[f] = vn; wa_f[4 * RS4 + f] = vs; }   // wa_n, wa_s
    }

    // W register cache, packed f32x2 along f (GEMV): warp covers d = warp*16+(lane&15)
    const int h = lane >> 4;
    const int d = warp * 16 + (lane & 15);
    ull Wreg2[32];
#pragma unroll
    for (int i = 0; i < 32; i++) {
        int f = h * 64 + 2 * i;
        unsigned lo = __float_as_uint(W[(size_t)f * 128 + d]);
        unsigned hi = __float_as_uint(W[(size_t)(f + 1) * 128 + d]);
        Wreg2[i] = ((ull)hi << 32) | lo;
    }
    __syncthreads();    // mbars + wa visible

    // parallel slot fill: 8 threads per slot, 3-4 TMA copies each
    auto group_fill = [&](int c, int j, int sub) {
        int grp = c % NGRP;
        int r0  = b + 4 * c * G;
        unsigned mb = mbar_base + 8 * grp;
        if (j == 0 && sub == 0 && r0 < BH) {
            int nv = (BH - 1 - r0) / G + 1;
            nv = (nv > 4) ? 4 : nv;
            mbar_expect_tx(mb, (unsigned)(nv * ROW_BYTES));
        }
        int row = r0 + j * G;
        if (row < BH) {
            unsigned dst = xs_base + (unsigned)(grp * 4 + j) * (SLOT_F4 * 16);
            const float* xn = x_neigh + (size_t)row * 3200;
#pragma unroll 1
            for (int rr = sub; rr < 25; rr += 8)
                tma_bulk_1d(dst + rr * (RS4 * 16), xn + rr * 128, 512, mb);
            if (sub == 0)
                tma_bulk_1d(dst + 25 * (RS4 * 16), x_self + (size_t)row * 128, 512, mb);
        }
    };

    // initial fill: consumption groups 0,1,2 (12 slots, 96 threads)
    if (t < 96) group_fill(t >> 5, (t >> 3) & 3, t & 7);

    // ---------------- main loop: 8 rows per iteration, 1 row per warp ----------------
    for (int i = 0; i < MAXIT; i++) {
        const int myrow = b + (8 * i + warp) * G;
        if (myrow < BH) {
            const int c   = 2 * i + (warp >> 2);
            const int grp = c % NGRP;
            mbar_wait(mbar_base + 8 * grp, (unsigned)((c / NGRP) & 1));

            const float4* sp = &xs[(grp * 4 + (warp & 3)) * SLOT_F4];

            // ---- scores: lane k owns dot k (0-24 neigh, 25 self·wa_n, 26 self·wa_s)
            const int rowk = (lane < 25) ? lane : 25;
            const float4* xr = sp + rowk * RS4;
            const float4* wv = &wa4[(lane == 26) ? RS4 : 0];
            float a0 = 0.f, a1 = 0.f, a2 = 0.f, a3 = 0.f;
#pragma unroll
            for (int m = 0; m < 32; m += 2) {
                float4 x0 = xr[m],     w0 = wv[m];
                float4 x1 = xr[m + 1], w1 = wv[m + 1];
                a0 = fmaf(x0.x, w0.x, a0); a0 = fmaf(x0.y, w0.y, a0);
                a1 = fmaf(x0.z, w0.z, a1); a1 = fmaf(x0.w, w0.w, a1);
                a2 = fmaf(x1.x, w1.x, a2); a2 = fmaf(x1.y, w1.y, a2);
                a3 = fmaf(x1.z, w1.z, a3); a3 = fmaf(x1.w, w1.w, a3);
            }
            float v  = (a0 + a1) + (a2 + a3);
            float ss = __shfl_sync(0xffffffffu, v, 26);
            float u  = ss + v;
            u = (u > 0.f) ? u : 0.2f * u;                 // LeakyReLU(0.2)
            float e = (lane < 26) ? __expf(u) : 0.f;      // no-max softmax (validated)
            float z = e;
#pragma unroll
            for (int o = 16; o; o >>= 1) z += __shfl_xor_sync(0xffffffffu, z, o);
            const float rz = __fdividef(1.f, z);

            // ---- aggregation: lane covers f = 4*lane..4*lane+3, e via shfl.idx
            float c0 = 0.f, c1 = 0.f, c2 = 0.f, c3 = 0.f;
#pragma unroll
            for (int k2 = 0; k2 < 26; k2++) {
                float ek = __shfl_sync(0xffffffffu, e, k2);
                float4 xv = sp[k2 * RS4 + lane];          // coalesced, conflict-free
                c0 = fmaf(ek, xv.x, c0); c1 = fmaf(ek, xv.y, c1);
                c2 = fmaf(ek, xv.z, c2); c3 = fmaf(ek, xv.w, c3);
            }
            c0 *= rz; c1 *= rz; c2 *= rz; c3 *= rz;

            // interleaved store for the conflict-free GEMV read pattern
            float* xp = &xagg_il[i & 1][warp][0];
            const int Lb = (lane < 16) ? 8 * lane : 8 * (lane - 16) + 4;
            *reinterpret_cast<float2*>(&xp[Lb])     = make_float2(c0, c1);
            *reinterpret_cast<float2*>(&xp[Lb + 2]) = make_float2(c2, c3);
        }
        __syncthreads();    // xagg ready; tiles of groups (2i)%3,(2i+1)%3 dead

        // refill the two consumed groups (c = 2i+3, 2i+4), 64 threads
        if (t < 64) group_fill(2 * i + 3 + (t >> 5), (t >> 3) & 3, t & 7);

        // ---- GEMV: all warps, 8 rows, from packed register W ----
        const float* xbuf = &xagg_il[i & 1][0][0];
#pragma unroll
        for (int r = 0; r < 8; r++) {
            const int orow = b + (8 * i + r) * G;
            if (orow < BH) {
                ull A0 = 0, A1 = 0;
                const float* xg = xbuf + r * 128;
#pragma unroll
                for (int ii = 0; ii < 16; ii++) {
                    longlong2 q = *reinterpret_cast<const longlong2*>(&xg[8 * ii + 4 * h]);
                    asm volatile("fma.rn.f32x2 %0, %1, %2, %0;\n"
                                 : "+l"(A0) : "l"((ull)q.x), "l"(Wreg2[2 * ii]));
                    asm volatile("fma.rn.f32x2 %0, %1, %2, %0;\n"
                                 : "+l"(A1) : "l"((ull)q.y), "l"(Wreg2[2 * ii + 1]));
                }
                float o = __uint_as_float((unsigned)A0) +
                          __uint_as_float((unsigned)(A0 >> 32)) +
                          __uint_as_float((unsigned)A1) +
                          __uint_as_float((unsigned)(A1 >> 32));
                o += __shfl_xor_sync(0xffffffffu, o, 16);   // combine f-halves
                if (h == 0)
                    out[(size_t)orow * 128 + d] = (o > 0.f) ? o : 0.f;
            }
        }
        // no second barrier: next iteration writes xagg_il[(i+1)&1] (double buffer)
    }
}

// ---------------------------------------------------------------------------
extern "C" void kernel_launch(void* const* d_in, const int* in_sizes, int n_in,
                              void* d_out, int out_size) {
    const float* x_self  = (const float*)d_in[0];   // [1024,32,128]
    const float* x_neigh = (const float*)d_in[1];   // [1024,32,25,128]
    const float* w_feat  = (const float*)d_in[2];   // [128,128]
    const float* a_self  = (const float*)d_in[3];   // [128,1]
    const float* a_neigh = (const float*)d_in[4];   // [128,1]
    float*       out     = (float*)d_out;           // [1024,32,128]

    fused_gat_kernel<<<G, THREADS>>>(x_self, x_neigh, w_feat,
                                     a_self, a_neigh, out);
}

// round 16
// speedup vs baseline: 1.4961x; 1.0118x over previous
#include <cuda_runtime.h>
#include <cstdint>
#include <math.h>

// Problem constants: B=1024, H=32, N=25, F=D=128
#define BH      32768
#define G       152                 // 1 block/SM x 152 SMs
#define THREADS 512                 // 16 warps; warp-per-row
#define RS4     33                  // padded row stride in float4 (132 floats)
#define SLOT_F4 (25 * RS4)          // 825 float4 = 13200 B (25 neigh rows only)
#define NSLOT   16
#define ROWB    12800               // TMA bytes per slot fill (25 x 512)
#define MAXIT   14                  // ceil(216 rows-per-block / 16)

typedef unsigned long long ull;

// ---------------------------------------------------------------------------
__device__ __forceinline__ void tma_bulk_1d(unsigned dst, const void* src,
                                            unsigned bytes, unsigned mbar) {
    asm volatile(
        "cp.async.bulk.shared::cluster.global.mbarrier::complete_tx::bytes "
        "[%0], [%1], %2, [%3];\n"
        :: "r"(dst), "l"(src), "r"(bytes), "r"(mbar) : "memory");
}
__device__ __forceinline__ void mbar_init(unsigned mbar, unsigned cnt) {
    asm volatile("mbarrier.init.shared.b64 [%0], %1;\n" :: "r"(mbar), "r"(cnt) : "memory");
}
__device__ __forceinline__ void mbar_expect_tx(unsigned mbar, unsigned bytes) {
    asm volatile("mbarrier.arrive.expect_tx.shared.b64 _, [%0], %1;\n"
                 :: "r"(mbar), "r"(bytes) : "memory");
}
__device__ __forceinline__ void mbar_wait(unsigned mbar, unsigned parity) {
    asm volatile(
        "{\n\t"
        ".reg .pred P;\n\t"
        "WL_%=:\n\t"
        "mbarrier.try_wait.parity.acquire.cta.shared::cta.b64 P, [%0], %1, 0x989680;\n\t"
        "@P bra WD_%=;\n\t"
        "bra WL_%=;\n\t"
        "WD_%=:\n\t"
        "}"
        :: "r"(mbar), "r"(parity) : "memory");
}

__global__ void __launch_bounds__(THREADS, 1)
fused_gat_kernel(const float* __restrict__ x_self,
                 const float* __restrict__ x_neigh,
                 const float* __restrict__ W,
                 const float* __restrict__ a_s,
                 const float* __restrict__ a_n,
                 float* __restrict__ out) {
    __shared__ __align__(16) float4 xs[NSLOT * SLOT_F4];   // 211,200 B tile ring
    __shared__ __align__(16) float4 wan4[32];              // wa_n (128 f)
    __shared__ __align__(16) float4 was4[32];              // wa_s
    __shared__ __align__(16) float  xagg[2][16][128];      // 16,384 B double-buffered
    __shared__ __align__(8)  ull    mbars[NSLOT];

    const int t    = threadIdx.x;
    const int warp = t >> 5;
    const int lane = t & 31;
    const int b    = blockIdx.x;

    const unsigned xs_base   = (unsigned)__cvta_generic_to_shared(&xs[0]);
    const unsigned mbar_base = (unsigned)__cvta_generic_to_shared(&mbars[0]);
    const unsigned mymb      = mbar_base + 8u * warp;
    const unsigned mydst     = xs_base + (unsigned)(warp * SLOT_F4) * 16u;

    if (t < NSLOT) mbar_init(mbar_base + 8u * t, 1);
    if (t == 0) asm volatile("fence.proxy.async.shared::cta;\n" ::: "memory");
    __syncthreads();

    // ---- initial fill: each warp fills its own slot (1 TMA per lane) ----
    {
        const int row0 = b + warp * G;                 // always < BH
        if (lane == 0) mbar_expect_tx(mymb, ROWB);
        const float* xn = x_neigh + (size_t)row0 * 3200;
        if (lane < 25)
            tma_bulk_1d(mydst + (unsigned)(lane * RS4) * 16u, xn + lane * 128, 512, mymb);
    }

    // ---- prologue: wa = W @ a  (4 threads per f) ----
    {
        const int f = t >> 2, sub = t & 3;
        const float* wr = W + (size_t)f * 128 + sub * 32;
        const float* as = a_s + sub * 32;
        const float* an = a_n + sub * 32;
        float vs = 0.f, vn = 0.f;
#pragma unroll 8
        for (int j = 0; j < 32; j++) {
            float w = wr[j];
            vs = fmaf(w, as[j], vs);
            vn = fmaf(w, an[j], vn);
        }
        vs += __shfl_xor_sync(0xffffffffu, vs, 1);
        vn += __shfl_xor_sync(0xffffffffu, vn, 1);
        vs += __shfl_xor_sync(0xffffffffu, vs, 2);
        vn += __shfl_xor_sync(0xffffffffu, vn, 2);
        if (sub == 0) {
            reinterpret_cast<float*>(wan4)[f] = vn;
            reinterpret_cast<float*>(was4)[f] = vs;
        }
    }

    // ---- W register cache (GEMV): warp covers d = warp*8+(lane&7); q = f-quarter
    const int q  = lane >> 3;
    const int dd = warp * 8 + (lane & 7);
    ull Wreg2[16];
#pragma unroll
    for (int i = 0; i < 16; i++) {
        int f = q * 32 + 2 * i;
        unsigned lo = __float_as_uint(W[(size_t)f * 128 + dd]);
        unsigned hi = __float_as_uint(W[(size_t)(f + 1) * 128 + dd]);
        Wreg2[i] = ((ull)hi << 32) | lo;
    }
    __syncthreads();    // wa visible

    // ---------------- main loop: 16 rows per iteration, 1 row per warp ----------------
    for (int i = 0; i < MAXIT; i++) {
        const int myrow = b + (16 * i + warp) * G;
        if (myrow < BH) {
            mbar_wait(mymb, (unsigned)(i & 1));
            const float4* sp = &xs[warp * SLOT_F4];

            // ---- self dots from a coalesced LDG (kept in regs for agg) ----
            const float4 x0 = reinterpret_cast<const float4*>(
                                  x_self + (size_t)myrow * 128)[lane];
            const float4 wn = wan4[lane];
            const float4 ws = was4[lane];
            float sn, ssv;
            sn  =      x0.x * wn.x;  sn  = fmaf(x0.y, wn.y, sn);
            sn  = fmaf(x0.z, wn.z, sn);  sn  = fmaf(x0.w, wn.w, sn);
            ssv =      x0.x * ws.x;  ssv = fmaf(x0.y, ws.y, ssv);
            ssv = fmaf(x0.z, ws.z, ssv); ssv = fmaf(x0.w, ws.w, ssv);
#pragma unroll
            for (int o = 16; o; o >>= 1) {
                sn  += __shfl_xor_sync(0xffffffffu, sn, o);
                ssv += __shfl_xor_sync(0xffffffffu, ssv, o);
            }
            float u25 = ssv + sn;
            u25 = (u25 > 0.f) ? u25 : 0.2f * u25;
            const float e25 = __expf(u25);

            // ---- neighbour scores: lane k owns dot k (k<25) ----
            const int rowk = (lane < 25) ? lane : 24;
            const float4* xr = sp + rowk * RS4;
            float a0 = 0.f, a1 = 0.f, a2 = 0.f, a3 = 0.f;
#pragma unroll
            for (int m = 0; m < 32; m += 2) {
                float4 xA = xr[m],     wA = wan4[m];          // wa: broadcast LDS
                float4 xB = xr[m + 1], wB = wan4[m + 1];
                a0 = fmaf(xA.x, wA.x, a0); a0 = fmaf(xA.y, wA.y, a0);
                a1 = fmaf(xA.z, wA.z, a1); a1 = fmaf(xA.w, wA.w, a1);
                a2 = fmaf(xB.x, wB.x, a2); a2 = fmaf(xB.y, wB.y, a2);
                a3 = fmaf(xB.z, wB.z, a3); a3 = fmaf(xB.w, wB.w, a3);
            }
            float u = ssv + (a0 + a1) + (a2 + a3);
            u = (u > 0.f) ? u : 0.2f * u;                     // LeakyReLU(0.2)
            const float e = (lane < 25) ? __expf(u) : 0.f;    // no-max softmax (validated)
            float z = e;
#pragma unroll
            for (int o = 16; o; o >>= 1) z += __shfl_xor_sync(0xffffffffu, z, o);
            z += e25;
            const float rz = __fdividef(1.f, z);

            // ---- aggregation: lane covers f = 4*lane..4*lane+3 ----
            float c0 = e25 * x0.x, c1 = e25 * x0.y,
                  c2 = e25 * x0.z, c3 = e25 * x0.w;
#pragma unroll
            for (int k2 = 0; k2 < 25; k2++) {
                float ek = __shfl_sync(0xffffffffu, e, k2);
                float4 xv = sp[k2 * RS4 + lane];              // 4-way max: free
                c0 = fmaf(ek, xv.x, c0); c1 = fmaf(ek, xv.y, c1);
                c2 = fmaf(ek, xv.z, c2); c3 = fmaf(ek, xv.w, c3);
            }
            c0 *= rz; c1 *= rz; c2 *= rz; c3 *= rz;

            // store xagg (operands data-depend on ALL slot reads -> slot is dead)
            reinterpret_cast<float4*>(&xagg[i & 1][warp][0])[lane] =
                make_float4(c0, c1, c2, c3);

            // ---- refill own slot for iteration i+1 (warp-local pipeline) ----
            const int nrow = myrow + 16 * G;
            if (nrow < BH) {
                if (lane == 0) mbar_expect_tx(mymb, ROWB);
                const float* xn = x_neigh + (size_t)nrow * 3200;
                if (lane < 25)
                    tma_bulk_1d(mydst + (unsigned)(lane * RS4) * 16u,
                                xn + lane * 128, 512, mymb);
            }
        }
        __syncthreads();               // xagg of all 16 rows visible

        // ---- GEMV: every warp, all 16 rows, from packed register W ----
#pragma unroll 4
        for (int r = 0; r < 16; r++) {
            const int orow = b + (16 * i + r) * G;
            if (orow < BH) {
                ull A0 = 0, A1 = 0;
                const float* xg = &xagg[i & 1][r][q * 32];
#pragma unroll
                for (int j = 0; j < 8; j++) {
                    longlong2 qq = *reinterpret_cast<const longlong2*>(&xg[4 * j]);
                    asm volatile("fma.rn.f32x2 %0, %1, %2, %0;\n"
                                 : "+l"(A0) : "l"((ull)qq.x), "l"(Wreg2[2 * j]));
                    asm volatile("fma.rn.f32x2 %0, %1, %2, %0;\n"
                                 : "+l"(A1) : "l"((ull)qq.y), "l"(Wreg2[2 * j + 1]));
                }
                float o = __uint_as_float((unsigned)A0) +
                          __uint_as_float((unsigned)(A0 >> 32)) +
                          __uint_as_float((unsigned)A1) +
                          __uint_as_float((unsigned)(A1 >> 32));
                o += __shfl_xor_sync(0xffffffffu, o, 8);      // combine 4 f-quarters
                o += __shfl_xor_sync(0xffffffffu, o, 16);
                if (q == 0)
                    out[(size_t)orow * 128 + dd] = (o > 0.f) ? o : 0.f;
            }
        }
        // no 2nd barrier: next iteration writes xagg[(i+1)&1] (double buffer)
    }
}

// ---------------------------------------------------------------------------
extern "C" void kernel_launch(void* const* d_in, const int* in_sizes, int n_in,
                              void* d_out, int out_size) {
    const float* x_self  = (const float*)d_in[0];   // [1024,32,128]
    const float* x_neigh = (const float*)d_in[1];   // [1024,32,25,128]
    const float* w_feat  = (const float*)d_in[2];   // [128,128]
    const float* a_self  = (const float*)d_in[3];   // [128,1]
    const float* a_neigh = (const float*)d_in[4];   // [128,1]
    float*       out     = (float*)d_out;           // [1024,32,128]

    fused_gat_kernel<<<G, THREADS>>>(x_self, x_neigh, w_feat,
                                     a_self, a_neigh, out);
}

// round 17
// speedup vs baseline: 2.1375x; 1.4287x over previous
#include <cuda_runtime.h>
#include <cstdint>
#include <math.h>

// Problem constants: B=1024, H=32, N=25, F=D=128
#define BH      32768
#define NK      26                  // softmax/aggregation length (self + 25)
#define FDIM    128
#define DDIM    128
#define GRIDSZ  304                 // 2 blocks/SM x 152 SMs (GB300)
#define THREADS 256
#define NPAIR   3                   // TMA ring depth in row-pairs
#define NSLOT   (2 * NPAIR)

#define ROW_FLOATS   (NK * FDIM)    // 3328 floats per staged row tile
#define SELF_BYTES   (FDIM * 4)     // 512
#define NEIGH_BYTES  (25 * FDIM * 4)// 12800
#define ROW_BYTES    (SELF_BYTES + NEIGH_BYTES) // 13312

typedef unsigned long long ull;

// ---------------------------------------------------------------------------
// TMA 1D bulk copy + mbarrier helpers
// ---------------------------------------------------------------------------
__device__ __forceinline__ void tma_bulk_1d(unsigned dst, const void* src,
                                            unsigned bytes, unsigned mbar) {
    asm volatile(
        "cp.async.bulk.shared::cluster.global.mbarrier::complete_tx::bytes "
        "[%0], [%1], %2, [%3];\n"
        :: "r"(dst), "l"(src), "r"(bytes), "r"(mbar) : "memory");
}
__device__ __forceinline__ void mbar_init(unsigned mbar, unsigned cnt) {
    asm volatile("mbarrier.init.shared.b64 [%0], %1;\n" :: "r"(mbar), "r"(cnt) : "memory");
}
__device__ __forceinline__ void mbar_expect_tx(unsigned mbar, unsigned bytes) {
    asm volatile("mbarrier.arrive.expect_tx.shared.b64 _, [%0], %1;\n"
                 :: "r"(mbar), "r"(bytes) : "memory");
}
__device__ __forceinline__ void mbar_wait(unsigned mbar, unsigned parity) {
    asm volatile(
        "{\n\t"
        ".reg .pred P;\n\t"
        "WL_%=:\n\t"
        "mbarrier.try_wait.parity.acquire.cta.shared::cta.b64 P, [%0], %1, 0x989680;\n\t"
        "@P bra WD_%=;\n\t"
        "bra WL_%=;\n\t"
        "WD_%=:\n\t"
        "}"
        :: "r"(mbar), "r"(parity) : "memory");
}

__global__ void __launch_bounds__(THREADS, 2)
fused_gat_kernel(const float* __restrict__ x_self,
                 const float* __restrict__ x_neigh,
                 const float* __restrict__ W,
                 const float* __restrict__ a_s,
                 const float* __restrict__ a_n,
                 float* __restrict__ out) {
    __shared__ __align__(128) float xs[NSLOT][ROW_FLOATS];      // ~80 KB ring
    __shared__ __align__(16)  float wa_s_sm[FDIM];
    __shared__ __align__(16)  float wa_n_sm[FDIM];
    __shared__ __align__(16)  float xpart[2][4][4][FDIM];        // dbl-buf per-warp partials
    __shared__ float zpart[2][4][4];                             // dbl-buf exp sums
    __shared__ __align__(16)  float xagg_il[2][4][FDIM];         // dbl-buf interleaved
    __shared__ __align__(8)   ull  mbars[NPAIR];

    const int t    = threadIdx.x;
    const int warp = t >> 5;
    const int lane = t & 31;

    const unsigned xs_base   = (unsigned)__cvta_generic_to_shared(&xs[0][0]);
    const unsigned mbar_base = (unsigned)__cvta_generic_to_shared(&mbars[0]);

    if (t == 0) {
#pragma unroll
        for (int i = 0; i < NPAIR; i++) mbar_init(mbar_base + 8 * i, 1);
        asm volatile("fence.proxy.async.shared::cta;\n" ::: "memory");
    }
    __syncthreads();

    const int G = GRIDSZ;
    auto issue_pair = [&](int p) {
        int rA = blockIdx.x + 2 * p * G;
        if (rA >= BH) return;
        int rB = rA + G;
        int nrows = (rB < BH) ? 2 : 1;
        unsigned mb = mbar_base + 8 * (p % NPAIR);
        unsigned s0 = xs_base + (unsigned)(2 * (p % NPAIR)) * (ROW_FLOATS * 4);
        mbar_expect_tx(mb, (unsigned)ROW_BYTES * nrows);
        tma_bulk_1d(s0,              x_self  + (size_t)rA * FDIM,      SELF_BYTES,  mb);
        tma_bulk_1d(s0 + SELF_BYTES, x_neigh + (size_t)rA * 25 * FDIM, NEIGH_BYTES, mb);
        if (nrows == 2) {
            unsigned s1 = s0 + ROW_FLOATS * 4;
            tma_bulk_1d(s1,              x_self  + (size_t)rB * FDIM,      SELF_BYTES,  mb);
            tma_bulk_1d(s1 + SELF_BYTES, x_neigh + (size_t)rB * 25 * FDIM, NEIGH_BYTES, mb);
        }
    };
    if (t == 0) { issue_pair(0); issue_pair(1); issue_pair(2); }

    // ---------------- prologue: wa = W @ a  (2 threads per f) ----------------
    {
        const int f  = t >> 1, hf = t & 1;
        const float* wr = W + (size_t)f * DDIM + hf * 64;
        const float* as = a_s + hf * 64;
        const float* an = a_n + hf * 64;
        float vs = 0.f, vn = 0.f;
#pragma unroll
        for (int j = 0; j < 64; j++) {
            float w = wr[j];
            vs = fmaf(w, as[j], vs);
            vn = fmaf(w, an[j], vn);
        }
        vs += __shfl_xor_sync(0xffffffffu, vs, 1);
        vn += __shfl_xor_sync(0xffffffffu, vn, 1);
        if (!hf) { wa_s_sm[f] = vs; wa_n_sm[f] = vn; }
    }

    // W register cache, packed f32x2 along f (for GEMV).
    const int h = lane >> 4;
    const int d = warp * 16 + (lane & 15);
    ull Wreg2[32];
#pragma unroll
    for (int i = 0; i < 32; i++) {
        int f = h * 64 + 2 * i;
        unsigned lo = __float_as_uint(W[(size_t)f * DDIM + d]);
        unsigned hi = __float_as_uint(W[(size_t)(f + 1) * DDIM + d]);
        Wreg2[i] = ((ull)hi << 32) | lo;
    }
    __syncthreads();     // wa_* visible

    // ---- 16-lane-dot layout: group g16 owns a dot; lane covers chunks lane, lane^16
    const int g16 = lane >> 4;          // dot group within warp (0/1)
    const int jx  = lane ^ 16;          // second chunk index
    const float4 wj0 = reinterpret_cast<const float4*>(wa_n_sm)[lane];
    const float4 wj1 = reinterpret_cast<const float4*>(wa_n_sm)[jx];
    const float4 wasL = reinterpret_cast<const float4*>(wa_s_sm)[lane];

    const int rsel = warp >> 2;        // warps 0-3 -> rows {0,2}, 4-7 -> rows {1,3}
    const int w4   = warp & 3;

    // process one staged row: online softmax + e-weighted aggregation
    auto do_row = [&](const float* slot, int r, int ib) {
        // self score ss = row0 . wa_s (full-warp dot)
        float4 x0 = reinterpret_cast<const float4*>(slot)[lane];
        float ss;
        ss =      x0.x * wasL.x;  ss = fmaf(x0.y, wasL.y, ss);
        ss = fmaf(x0.z, wasL.z, ss); ss = fmaf(x0.w, wasL.w, ss);
        ss += __shfl_xor_sync(0xffffffffu, ss, 16);
        ss += __shfl_xor_sync(0xffffffffu, ss, 8);
        ss += __shfl_xor_sync(0xffffffffu, ss, 4);
        ss += __shfl_xor_sync(0xffffffffu, ss, 2);
        ss += __shfl_xor_sync(0xffffffffu, ss, 1);

        float4 paA = make_float4(0.f, 0.f, 0.f, 0.f);
        float4 paB = make_float4(0.f, 0.f, 0.f, 0.f);
        float  z = 0.f;
#pragma unroll
        for (int P = 0; P < 4; P++) {
            const int k  = w4 + 8 * P + 4 * g16;   // group's dot index
            const int kc = (k < NK) ? k : 0;       // clamp (result discarded)
            const float4* row4 = reinterpret_cast<const float4*>(slot + kc * FDIM);
            float4 xa = row4[lane];
            float4 xb = row4[jx];
            float v;
            v =      xa.x * wj0.x;  v = fmaf(xa.y, wj0.y, v);
            v = fmaf(xa.z, wj0.z, v); v = fmaf(xa.w, wj0.w, v);
            v = fmaf(xb.x, wj1.x, v); v = fmaf(xb.y, wj1.y, v);
            v = fmaf(xb.z, wj1.z, v); v = fmaf(xb.w, wj1.w, v);
            v += __shfl_xor_sync(0xffffffffu, v, 8);
            v += __shfl_xor_sync(0xffffffffu, v, 4);
            v += __shfl_xor_sync(0xffffffffu, v, 2);
            v += __shfl_xor_sync(0xffffffffu, v, 1);
            if (k < NK) {
                float uu = ss + v;
                uu = (uu > 0.f) ? uu : 0.2f * uu;   // LeakyReLU(0.2)
                float e = __expf(uu);
                paA.x = fmaf(e, xa.x, paA.x); paA.y = fmaf(e, xa.y, paA.y);
                paA.z = fmaf(e, xa.z, paA.z); paA.w = fmaf(e, xa.w, paA.w);
                paB.x = fmaf(e, xb.x, paB.x); paB.y = fmaf(e, xb.y, paB.y);
                paB.z = fmaf(e, xb.z, paB.z); paB.w = fmaf(e, xb.w, paB.w);
                z += e;
            }
        }
        // combine the two 16-lane groups: partner's paB is MY chunk (lane)
        paA.x += __shfl_xor_sync(0xffffffffu, paB.x, 16);
        paA.y += __shfl_xor_sync(0xffffffffu, paB.y, 16);
        paA.z += __shfl_xor_sync(0xffffffffu, paB.z, 16);
        paA.w += __shfl_xor_sync(0xffffffffu, paB.w, 16);
        z += __shfl_xor_sync(0xffffffffu, z, 16);
        reinterpret_cast<float4*>(&xpart[ib][r][w4][0])[lane] = paA;
        if (lane == 0) zpart[ib][r][w4] = z;
    };

    // GEMV for 4 rows from buffer bufsel (packed register W; conflict-free LDS.128)
    auto gemv4 = [&](int baseRow, int bufsel) {
#pragma unroll
        for (int r = 0; r < 4; r++) {
            const int orow = baseRow + r * G;
            if (orow < BH) {
                ull A0 = 0, A1 = 0;
#pragma unroll
                for (int i = 0; i < 16; i++) {
                    longlong2 q = *reinterpret_cast<const longlong2*>(
                        &xagg_il[bufsel][r][8 * i + 4 * h]);
                    asm volatile("fma.rn.f32x2 %0, %1, %2, %0;\n"
                                 : "+l"(A0) : "l"((ull)q.x), "l"(Wreg2[2 * i]));
                    asm volatile("fma.rn.f32x2 %0, %1, %2, %0;\n"
                                 : "+l"(A1) : "l"((ull)q.y), "l"(Wreg2[2 * i + 1]));
                }
                float o = __uint_as_float((unsigned)A0) +
                          __uint_as_float((unsigned)(A0 >> 32)) +
                          __uint_as_float((unsigned)A1) +
                          __uint_as_float((unsigned)(A1 >> 32));
                o += __shfl_xor_sync(0xffffffffu, o, 16);   // combine f-halves
                if (h == 0)
                    out[(size_t)orow * DDIM + d] = (o > 0.f) ? o : 0.f;
            }
        }
    };

    // ---------------- main loop: 4 rows per iteration; GEMV deferred 1 iter ----
    int rowA = blockIdx.x;
    int p = 0, it = 0, prevRowA = 0;

    while (rowA < BH) {
        const int ib = it & 1;
        const bool rv1 = rowA + G     < BH;
        const bool rv2 = rowA + 2 * G < BH;
        const bool rv3 = rowA + 3 * G < BH;

        mbar_wait(mbar_base + 8 * (p % NPAIR), (unsigned)((p / NPAIR) & 1));
        if (rv2)
            mbar_wait(mbar_base + 8 * ((p + 1) % NPAIR),
                      (unsigned)(((p + 1) / NPAIR) & 1));

        const float* slotU = &xs[2 * (p % NPAIR) + rsel][0];
        const float* slotV = &xs[2 * ((p + 1) % NPAIR) + rsel][0];
        const bool wu = (rsel == 0) || rv1;
        const bool wv = rv2 && ((rsel == 0) || rv3);

        if (wu) do_row(slotU, rsel, ib);
        if (wv) do_row(slotV, rsel + 2, ib);
        __syncthreads();               // B3: partials visible; tiles dead

        // refill the two consumed pairs
        if (t == 0) { issue_pair(p + 3); issue_pair(p + 4); }

        // ---- reduce 4 partials, divide by Z -> interleaved xagg (this iter) ----
        {
            const int r  = t >> 6;     // row 0..3
            const int fp = t & 63;     // f-pair index
            const float* xp = &xpart[ib][r][0][2 * fp];
            ull q0 = *reinterpret_cast<const ull*>(xp);
            ull q1 = *reinterpret_cast<const ull*>(xp + FDIM);
            ull q2 = *reinterpret_cast<const ull*>(xp + 2 * FDIM);
            ull q3 = *reinterpret_cast<const ull*>(xp + 3 * FDIM);
            asm volatile("add.rn.f32x2 %0, %0, %1;\n" : "+l"(q0) : "l"(q1));
            asm volatile("add.rn.f32x2 %0, %0, %1;\n" : "+l"(q2) : "l"(q3));
            asm volatile("add.rn.f32x2 %0, %0, %1;\n" : "+l"(q0) : "l"(q2));
            float rz = __fdividef(1.f, zpart[ib][r][0] + zpart[ib][r][1]
                                     + zpart[ib][r][2] + zpart[ib][r][3]);
            ull rz2;
            asm volatile("mov.b64 %0, {%1, %1};\n" : "=l"(rz2) : "f"(rz));
            asm volatile("mul.rn.f32x2 %0, %0, %1;\n" : "+l"(q0) : "l"(rz2));
            const int sOff = (fp < 32) ? (8 * (fp >> 1) + 2 * (fp & 1))
                                       : (8 * ((fp - 32) >> 1) + 4 + 2 * (fp & 1));
            *reinterpret_cast<ull*>(&xagg_il[ib][r][sOff]) = q0;
        }

        // ---- deferred GEMV for PREVIOUS iteration (other buffer; no barrier) ----
        if (it > 0) gemv4(prevRowA, ib ^ 1);

        prevRowA = rowA;
        rowA += 4 * G;
        p += 2;
        it++;
    }

    // epilogue: final iteration's GEMV (needs its reduce visible block-wide)
    __syncthreads();
    gemv4(prevRowA, (it - 1) & 1);
}

// ---------------------------------------------------------------------------
extern "C" void kernel_launch(void* const* d_in, const int* in_sizes, int n_in,
                              void* d_out, int out_size) {
    const float* x_self  = (const float*)d_in[0];   // [1024,32,128]
    const float* x_neigh = (const float*)d_in[1];   // [1024,32,25,128]
    const float* w_feat  = (const float*)d_in[2];   // [128,128]
    const float* a_self  = (const float*)d_in[3];   // [128,1]
    const float* a_neigh = (const float*)d_in[4];   // [128,1]
    float*       out     = (float*)d_out;           // [1024,32,128]

    fused_gat_kernel<<<GRIDSZ, THREADS>>>(x_self, x_neigh, w_feat,
                                          a_self, a_neigh, out);
}